// round 8
// baseline (speedup 1.0000x reference)
#include <cuda_runtime.h>
#include <cuda_fp16.h>
#include <cstdint>

#define B 128
#define S 400
#define H 256
#define E 128
#define V 50000
#define PAD 250
#define VP 50250
#define H2 512
#define H3 768
#define NBLK 391            // ceil(V/128)
#define NBLK4 (NBLK*4)      // 32-wide v-chunks per batch row
#define WSTR 136            // fp16 elems per smem row (bank-conflict-free ldmatrix)
#define CH 50               // seq rows per attention chunk
#define NCH 8               // chunks per batch row (CH*NCH == S)

// Output layout: concat of flattened (h_new, p_final, p_gen, p_vocab, att_dist)
#define OUT_HNEW   0
#define OUT_PFINAL (B*H)
#define OUT_PGEN   (OUT_PFINAL + B*VP)
#define OUT_PVOCAB (OUT_PGEN + B)
#define OUT_ATT    (OUT_PVOCAB + B*V)

#define SMEM_D1 (2*128*WSTR*2 + 128*4)          // Wh, Dh fp16 tiles + bias row
#define SMEM_P  ((CH*H + 3*H + 64)*4)           // enc chunk + wh/av/ch + scores

// ---------------- scratch (static device globals; no allocation) -------------
__device__ float g_x[B*E];
__device__ float g_hnew[B*H];
__device__ float g_gsum[B*H3];
__device__ float g_ghn[B*H];
__device__ float g_esc[B*S];         // exp(score - m_chunk)
__device__ float g_cmax[B*NCH];
__device__ float g_csum[B*NCH];
__device__ float g_pctx[B*NCH*H];    // partial contexts
__device__ float g_ad[B*S];
__device__ float g_decH[B*E];        // [b][e] fp32
__device__ float g_logits[B*V];      // holds e = exp(logit - m_chunk)
__device__ float g_pmax[B*NBLK4];
__device__ float g_psum[B*NBLK4];
__device__ float g_scale[B*NBLK4];   // exp(m_chunk - M)/Z
__device__ float g_pgen[B];

__device__ __forceinline__ float tanh_hw(float x) {
    float y;
    asm("tanh.approx.f32 %0, %1;" : "=f"(y) : "f"(x));
    return y;
}

__device__ __forceinline__ uint32_t smem_u32(const void* p) {
    return (uint32_t)__cvta_generic_to_shared(p);
}

// ---------------- A1: GRU gate GEMMs (embedding gather fused in) -------------
__global__ __launch_bounds__(256) void k_gates(
    const int* __restrict__ tok,    const float* __restrict__ emb,
    const float* __restrict__ hprev, const float* __restrict__ Wih,
    const float* __restrict__ Whh,  const float* __restrict__ bih,
    const float* __restrict__ bhh) {
    __shared__ float xhT[384*20];
    __shared__ float wT[64*65];
    __shared__ int   s_tok[16];
    int j0 = blockIdx.x*64, b0 = blockIdx.y*16;
    int tid = threadIdx.x;

    if (tid < 16) s_tok[tid] = tok[b0 + tid];
    __syncthreads();

    for (int i = tid; i < 16*384; i += 256) {
        int bl = i/384, k = i%384;
        float v = (k < 128) ? emb[(size_t)s_tok[bl]*E + k] : hprev[(b0+bl)*H + (k-128)];
        xhT[k*20 + bl] = v;
        if (blockIdx.x == 0 && k < 128) g_x[(b0+bl)*E + k] = v;
    }

    int j_loc = tid & 63, bq = tid >> 6;
    int j = j0 + j_loc;
    bool isN = (j >= 2*H);
    float acc[4]  = {0.f,0.f,0.f,0.f};
    float accn[4] = {0.f,0.f,0.f,0.f};

    for (int kt = 0; kt < 384; kt += 64) {
        __syncthreads();
        for (int i = tid; i < 64*64; i += 256) {
            int jl = i >> 6, kk = i & 63;
            int k = kt + kk, jj = j0 + jl;
            float w = (k < 128) ? Wih[(size_t)jj*E + k] : Whh[(size_t)jj*H + (k-128)];
            wT[kk*65 + jl] = w;
        }
        __syncthreads();
        if (kt < 128) {
            #pragma unroll 8
            for (int kk = 0; kk < 64; kk++) {
                float w = wT[kk*65 + j_loc];
                float4 xv = *(const float4*)&xhT[(kt+kk)*20 + bq*4];
                acc[0] = fmaf(w, xv.x, acc[0]); acc[1] = fmaf(w, xv.y, acc[1]);
                acc[2] = fmaf(w, xv.z, acc[2]); acc[3] = fmaf(w, xv.w, acc[3]);
            }
        } else {
            #pragma unroll 8
            for (int kk = 0; kk < 64; kk++) {
                float w = wT[kk*65 + j_loc];
                float4 xv = *(const float4*)&xhT[(kt+kk)*20 + bq*4];
                acc[0] = fmaf(w, xv.x, acc[0]); acc[1] = fmaf(w, xv.y, acc[1]);
                acc[2] = fmaf(w, xv.z, acc[2]); acc[3] = fmaf(w, xv.w, acc[3]);
                accn[0] = fmaf(w, xv.x, accn[0]); accn[1] = fmaf(w, xv.y, accn[1]);
                accn[2] = fmaf(w, xv.z, accn[2]); accn[3] = fmaf(w, xv.w, accn[3]);
            }
        }
    }
    float bs = bih[j] + bhh[j];
    #pragma unroll
    for (int i = 0; i < 4; i++) {
        int b = b0 + bq*4 + i;
        g_gsum[b*H3 + j] = acc[i] + bs;
        if (isN) g_ghn[b*H + (j - 2*H)] = accn[i] + bhh[j];
    }
}

// ---------------- B: GRU elementwise + scores + chunk softmax + partial ctx --
extern __shared__ float smem_p[];
__global__ __launch_bounds__(256) void k_part(
    const float* __restrict__ enc, const float* __restrict__ wh,
    const float* __restrict__ ws,  const float* __restrict__ ab,
    const float* __restrict__ av,  const float* __restrict__ hprev,
    float* __restrict__ out) {
    float* sEnc = smem_p;               // [CH][H]
    float* s_wh = sEnc + CH*H;
    float* s_av = s_wh + H;
    float* s_ch = s_av + H;
    float* sSc  = s_ch + H;             // [CH] scores then exp values

    int c = blockIdx.x, b = blockIdx.y;
    int tid = threadIdx.x;
    int warp = tid >> 5, lane = tid & 31;

    // recompute GRU elementwise for this row (redundant across c; trivial)
    {
        float gr = g_gsum[b*H3 + tid];
        float gz = g_gsum[b*H3 + H + tid];
        float gn = g_gsum[b*H3 + 2*H + tid];
        float hn = g_ghn[b*H + tid];
        float r = 1.f/(1.f + __expf(-gr));
        float z = 1.f/(1.f + __expf(-gz));
        float n = tanhf(gn + (r - 1.f)*hn);
        float h = (1.f - z)*n + z*hprev[b*H + tid];
        s_ch[tid] = fmaf(ws[tid], h, ab[0]);
        if (c == 0) { g_hnew[b*H + tid] = h; out[OUT_HNEW + b*H + tid] = h; }
    }
    s_wh[tid] = wh[tid];
    s_av[tid] = av[tid];

    {
        const float4* src = (const float4*)(enc + ((size_t)b*S + c*CH)*H);
        float4* dst = (float4*)sEnc;
        #pragma unroll
        for (int i = tid; i < CH*H/4; i += 256) dst[i] = src[i];
    }
    __syncthreads();

    for (int s = warp; s < CH; s += 8) {
        const float* ep = sEnc + s*H;
        int h0 = lane*4;
        float acc = 0.f;
        float4 e0 = *(const float4*)&ep[h0];
        float4 w0 = *(const float4*)&s_wh[h0];
        float4 c0 = *(const float4*)&s_ch[h0];
        float4 a0 = *(const float4*)&s_av[h0];
        acc = fmaf(tanh_hw(fmaf(w0.x, e0.x, c0.x)), a0.x, acc);
        acc = fmaf(tanh_hw(fmaf(w0.y, e0.y, c0.y)), a0.y, acc);
        acc = fmaf(tanh_hw(fmaf(w0.z, e0.z, c0.z)), a0.z, acc);
        acc = fmaf(tanh_hw(fmaf(w0.w, e0.w, c0.w)), a0.w, acc);
        float4 e1 = *(const float4*)&ep[h0 + 128];
        float4 w1 = *(const float4*)&s_wh[h0 + 128];
        float4 c1 = *(const float4*)&s_ch[h0 + 128];
        float4 a1 = *(const float4*)&s_av[h0 + 128];
        acc = fmaf(tanh_hw(fmaf(w1.x, e1.x, c1.x)), a1.x, acc);
        acc = fmaf(tanh_hw(fmaf(w1.y, e1.y, c1.y)), a1.y, acc);
        acc = fmaf(tanh_hw(fmaf(w1.z, e1.z, c1.z)), a1.z, acc);
        acc = fmaf(tanh_hw(fmaf(w1.w, e1.w, c1.w)), a1.w, acc);
        #pragma unroll
        for (int o = 16; o; o >>= 1) acc += __shfl_xor_sync(0xffffffffu, acc, o);
        if (lane == 0) sSc[s] = acc;
    }
    __syncthreads();

    if (warp == 0) {
        float v0 = (lane      < CH) ? sSc[lane]      : -1e30f;
        float v1 = (lane + 32 < CH) ? sSc[lane + 32] : -1e30f;
        float m = fmaxf(v0, v1);
        #pragma unroll
        for (int o = 16; o; o >>= 1) m = fmaxf(m, __shfl_xor_sync(0xffffffffu, m, o));
        float e0 = (lane      < CH) ? __expf(v0 - m) : 0.f;
        float e1 = (lane + 32 < CH) ? __expf(v1 - m) : 0.f;
        if (lane      < CH) { sSc[lane]      = e0; g_esc[b*S + c*CH + lane]      = e0; }
        if (lane + 32 < CH) { sSc[lane + 32] = e1; g_esc[b*S + c*CH + lane + 32] = e1; }
        float s = e0 + e1;
        #pragma unroll
        for (int o = 16; o; o >>= 1) s += __shfl_xor_sync(0xffffffffu, s, o);
        if (lane == 0) { g_cmax[b*NCH + c] = m; g_csum[b*NCH + c] = s; }
    }
    __syncthreads();

    {
        float c0 = 0.f, c1 = 0.f, c2 = 0.f, c3 = 0.f;
        #pragma unroll 4
        for (int s = 0; s < 48; s += 4) {
            c0 = fmaf(sSc[s],   sEnc[(s)*H + tid],   c0);
            c1 = fmaf(sSc[s+1], sEnc[(s+1)*H + tid], c1);
            c2 = fmaf(sSc[s+2], sEnc[(s+2)*H + tid], c2);
            c3 = fmaf(sSc[s+3], sEnc[(s+3)*H + tid], c3);
        }
        c0 = fmaf(sSc[48], sEnc[48*H + tid], c0);
        c1 = fmaf(sSc[49], sEnc[49*H + tid], c1);
        g_pctx[(b*NCH + c)*H + tid] = (c0 + c1) + (c2 + c3);
    }
}

// ---------------- C: combine partials + att_dist + dec_h + p_gen -------------
// grid (8, B). Each block computes dctx (cheap) and a 16-row GEMV slice;
// block ez==0 additionally emits att_dist and p_gen.
__global__ __launch_bounds__(256) void k_comb_att(
    const float* __restrict__ outhw, const float* __restrict__ outhb,
    const float* __restrict__ genw,  const float* __restrict__ genb,
    float* __restrict__ out) {
    __shared__ __align__(16) float dctx[2*H];
    __shared__ float red[256];
    __shared__ float sW[NCH];
    int ez = blockIdx.x, b = blockIdx.y;
    int tid = threadIdx.x;
    int warp = tid >> 5, lane = tid & 31;

    if (warp == 0) {
        float m = (lane < NCH) ? g_cmax[b*NCH + lane] : -1e30f;
        float s = (lane < NCH) ? g_csum[b*NCH + lane] : 0.f;
        float sm = m;
        #pragma unroll
        for (int o = 16; o; o >>= 1) sm = fmaxf(sm, __shfl_xor_sync(0xffffffffu, sm, o));
        float t = s*__expf(m - sm);
        float L = t;
        #pragma unroll
        for (int o = 16; o; o >>= 1) L += __shfl_xor_sync(0xffffffffu, L, o);
        if (lane < NCH) sW[lane] = __expf(m - sm)/L;
    }
    __syncthreads();

    {
        float ctx = 0.f;
        #pragma unroll
        for (int c = 0; c < NCH; c++) ctx = fmaf(g_pctx[(b*NCH + c)*H + tid], sW[c], ctx);
        dctx[H + tid] = ctx;
        dctx[tid] = g_hnew[b*H + tid];
    }
    __syncthreads();

    // dec_h GEMV slice: e in [ez*16, ez*16+16), 2 rows per warp
    {
        const float4* dc4 = (const float4*)dctx;
        float4 d0 = dc4[lane], d1 = dc4[lane+32], d2 = dc4[lane+64], d3 = dc4[lane+96];
        #pragma unroll
        for (int i = 0; i < 2; i++) {
            int e = ez*16 + warp*2 + i;
            const float4* wr = (const float4*)(outhw + (size_t)e*H2);
            float4 w0 = wr[lane], w1 = wr[lane+32], w2 = wr[lane+64], w3 = wr[lane+96];
            float s0 = fmaf(w0.w, d0.w, fmaf(w0.z, d0.z, fmaf(w0.y, d0.y, w0.x*d0.x)));
            float s1 = fmaf(w1.w, d1.w, fmaf(w1.z, d1.z, fmaf(w1.y, d1.y, w1.x*d1.x)));
            float s2 = fmaf(w2.w, d2.w, fmaf(w2.z, d2.z, fmaf(w2.y, d2.y, w2.x*d2.x)));
            float s3 = fmaf(w3.w, d3.w, fmaf(w3.z, d3.z, fmaf(w3.y, d3.y, w3.x*d3.x)));
            float a = (s0 + s1) + (s2 + s3);
            #pragma unroll
            for (int o = 16; o; o >>= 1) a += __shfl_xor_sync(0xffffffffu, a, o);
            if (lane == 0) g_decH[b*E + e] = a + outhb[e];
        }
    }

    if (ez == 0) {
        for (int i = tid; i < S; i += 256) {
            float a = g_esc[b*S + i]*sW[i/CH];
            g_ad[b*S + i] = a;
            out[OUT_ATT + b*S + i] = a;
        }
        float p = 0.f;
        for (int i = tid; i < 2*H + E; i += 256) {
            float cv = (i < 2*H) ? dctx[i] : g_x[b*E + (i - 2*H)];
            p = fmaf(cv, genw[i], p);
        }
        red[tid] = p; __syncthreads();
        for (int o = 128; o; o >>= 1) { if (tid < o) red[tid] += red[tid+o]; __syncthreads(); }
        if (tid == 0) {
            float pg = 1.f/(1.f + __expf(-(red[0] + genb[0])));
            g_pgen[b] = pg;
            out[OUT_PGEN + b] = pg;
        }
    }
}

// ---------------- D: vocab GEMM; stores e = exp(logit - m_chunk) -------------
extern __shared__ char smem_d[];
__global__ __launch_bounds__(256, 2) void k_logits(
    const float* __restrict__ Wv, const float* __restrict__ bv) {
    __half* sWh = (__half*)smem_d;
    __half* sDh = sWh + 128*WSTR;
    float* sBias = (float*)(smem_d + 2*128*WSTR*2);
    __shared__ float2 sPart[8][64];   // per-warp(v-chunk, b-half) per-b (max,sum)

    int tid = threadIdx.x;
    int v0 = blockIdx.x*128;
    bool full = (v0 + 128 <= V);

    if (full) {
        for (int i = tid; i < 128*32; i += 256) {
            int r = i >> 5, kq = i & 31;
            float4 w4 = *(const float4*)&Wv[(size_t)(v0 + r)*E + kq*4];
            __half2* ph = (__half2*)&sWh[r*WSTR + kq*4];
            ph[0] = __half2(__float2half(w4.x), __float2half(w4.y));
            ph[1] = __half2(__float2half(w4.z), __float2half(w4.w));
        }
    } else {
        for (int i = tid; i < 128*128; i += 256) {
            int r = i >> 7, k = i & 127;
            int v = v0 + r;
            float w = (v < V) ? Wv[(size_t)v*E + k] : 0.f;
            sWh[r*WSTR + k] = __float2half(w);
        }
    }
    for (int i = tid; i < 128*32; i += 256) {
        int bb = i >> 5, kq = i & 31;
        float4 d4 = *(const float4*)&g_decH[bb*E + kq*4];
        __half2* ph = (__half2*)&sDh[bb*WSTR + kq*4];
        ph[0] = __half2(__float2half(d4.x), __float2half(d4.y));
        ph[1] = __half2(__float2half(d4.z), __float2half(d4.w));
    }
    if (tid < 128) sBias[tid] = (v0 + tid < V) ? bv[v0 + tid] : 0.f;
    __syncthreads();

    int warp = tid >> 5, lane = tid & 31;
    int mBase = (warp & 3)*32;     // vocab offset in tile
    int nBase = (warp >> 2)*64;    // batch offset in tile

    float acc[2][8][4];
    #pragma unroll
    for (int mi = 0; mi < 2; mi++)
        #pragma unroll
        for (int j = 0; j < 8; j++)
            #pragma unroll
            for (int q = 0; q < 4; q++) acc[mi][j][q] = 0.f;

    int aRow = mBase + (lane & 7) + ((lane >> 3) & 1)*8;
    int aK   = (lane >> 4)*8;
    int bRow = nBase + (lane & 7) + (lane >> 4)*8;
    int bK   = ((lane >> 3) & 1)*8;

    uint32_t uWh = smem_u32(sWh) + (uint32_t)(aRow*WSTR + aK)*2;
    uint32_t uDh = smem_u32(sDh) + (uint32_t)(bRow*WSTR + bK)*2;

    #pragma unroll
    for (int k0 = 0; k0 < 128; k0 += 16) {
        uint32_t ah[2][4];
        #pragma unroll
        for (int mi = 0; mi < 2; mi++) {
            uint32_t adh = uWh + (uint32_t)(mi*16*WSTR + k0)*2;
            asm volatile("ldmatrix.sync.aligned.m8n8.x4.shared.b16 {%0,%1,%2,%3}, [%4];"
                : "=r"(ah[mi][0]), "=r"(ah[mi][1]), "=r"(ah[mi][2]), "=r"(ah[mi][3])
                : "r"(adh));
        }
        #pragma unroll
        for (int jp = 0; jp < 4; jp++) {
            uint32_t bfr[4];
            uint32_t bd = uDh + (uint32_t)(jp*16*WSTR + k0)*2;
            asm volatile("ldmatrix.sync.aligned.m8n8.x4.shared.b16 {%0,%1,%2,%3}, [%4];"
                : "=r"(bfr[0]), "=r"(bfr[1]), "=r"(bfr[2]), "=r"(bfr[3])
                : "r"(bd));
            #pragma unroll
            for (int mi = 0; mi < 2; mi++) {
                asm volatile(
                    "mma.sync.aligned.m16n8k16.row.col.f32.f16.f16.f32 "
                    "{%0,%1,%2,%3}, {%4,%5,%6,%7}, {%8,%9}, {%0,%1,%2,%3};"
                    : "+f"(acc[mi][2*jp][0]), "+f"(acc[mi][2*jp][1]),
                      "+f"(acc[mi][2*jp][2]), "+f"(acc[mi][2*jp][3])
                    : "r"(ah[mi][0]), "r"(ah[mi][1]), "r"(ah[mi][2]), "r"(ah[mi][3]),
                      "r"(bfr[0]), "r"(bfr[1]));
                asm volatile(
                    "mma.sync.aligned.m16n8k16.row.col.f32.f16.f16.f32 "
                    "{%0,%1,%2,%3}, {%4,%5,%6,%7}, {%8,%9}, {%0,%1,%2,%3};"
                    : "+f"(acc[mi][2*jp+1][0]), "+f"(acc[mi][2*jp+1][1]),
                      "+f"(acc[mi][2*jp+1][2]), "+f"(acc[mi][2*jp+1][3])
                    : "r"(ah[mi][0]), "r"(ah[mi][1]), "r"(ah[mi][2]), "r"(ah[mi][3]),
                      "r"(bfr[2]), "r"(bfr[3]));
            }
        }
    }

    // bias add + invalid mask
    int nvalid = min(128, V - v0);
    float bias_v[2][2];
    #pragma unroll
    for (int mi = 0; mi < 2; mi++)
        #pragma unroll
        for (int qh = 0; qh < 2; qh++)
            bias_v[mi][qh] = sBias[mBase + 16*mi + (lane >> 2) + 8*qh];
    #pragma unroll
    for (int mi = 0; mi < 2; mi++)
        #pragma unroll
        for (int j = 0; j < 8; j++)
            #pragma unroll
            for (int q = 0; q < 4; q++) {
                int vl = mBase + 16*mi + (lane >> 2) + 8*(q >> 1);
                float val = acc[mi][j][q] + bias_v[mi][q >> 1];
                acc[mi][j][q] = (vl < nvalid) ? val : -1e30f;
            }

    // per (b, 32-v-chunk): max, then store e = exp(val - m), accumulate sum
    #pragma unroll
    for (int j = 0; j < 8; j++)
        #pragma unroll
        for (int ql = 0; ql < 2; ql++) {
            float m = fmaxf(fmaxf(acc[0][j][ql], acc[0][j][ql+2]),
                            fmaxf(acc[1][j][ql], acc[1][j][ql+2]));
            #pragma unroll
            for (int o = 4; o <= 16; o <<= 1) m = fmaxf(m, __shfl_xor_sync(0xffffffffu, m, o));
            int bb = nBase + 8*j + 2*(lane & 3) + ql;
            float s = 0.f;
            #pragma unroll
            for (int mi = 0; mi < 2; mi++)
                #pragma unroll
                for (int qh = 0; qh < 2; qh++) {
                    float e = __expf(acc[mi][j][ql + 2*qh] - m);
                    s += e;
                    int vl = mBase + 16*mi + (lane >> 2) + 8*qh;
                    if (vl < nvalid) g_logits[(size_t)bb*V + v0 + vl] = e;
                }
            #pragma unroll
            for (int o = 4; o <= 16; o <<= 1) s += __shfl_xor_sync(0xffffffffu, s, o);
            if ((lane >> 2) == 0)
                sPart[warp][8*j + 2*(lane & 3) + ql] = make_float2(m, s);
        }
    __syncthreads();

    // write per-(b, chunk) partials: 128 b x 4 chunks
    for (int idx = tid; idx < 512; idx += 256) {
        int bb = idx & 127, ch = idx >> 7;
        float2 p = sPart[(bb >> 6)*4 + ch][bb & 63];
        g_pmax[(size_t)bb*NBLK4 + blockIdx.x*4 + ch] = p.x;
        g_psum[(size_t)bb*NBLK4 + blockIdx.x*4 + ch] = p.y;
    }
}

// ---------------- D2: global (M, Z) + per-chunk scales ------------------------
__global__ __launch_bounds__(256) void k_comb() {
    __shared__ float sm[256], ss[256];
    int b = blockIdx.x, tid = threadIdx.x;
    float m = -1e30f, s = 0.f;
    for (int i = tid; i < NBLK4; i += 256) {
        float pm = g_pmax[b*NBLK4 + i], ps = g_psum[b*NBLK4 + i];
        if (pm > m) { s = s*__expf(m - pm) + ps; m = pm; }
        else          s += ps*__expf(pm - m);
    }
    sm[tid] = m; ss[tid] = s; __syncthreads();
    for (int o = 128; o; o >>= 1) {
        if (tid < o) {
            float m1 = sm[tid], s1 = ss[tid];
            float m2 = sm[tid+o], s2 = ss[tid+o];
            float nm = fmaxf(m1, m2);
            sm[tid] = nm;
            ss[tid] = s1*__expf(m1 - nm) + s2*__expf(m2 - nm);
        }
        __syncthreads();
    }
    float M = sm[0], invZ = 1.f/ss[0];
    for (int i = tid; i < NBLK4; i += 256)
        g_scale[b*NBLK4 + i] = __expf(g_pmax[b*NBLK4 + i] - M)*invZ;
}

// ---------------- E: p_vocab + p_final (pure streaming multiply) --------------
__global__ __launch_bounds__(256) void k_final(float* __restrict__ out) {
    int b = blockIdx.y;
    int v = (blockIdx.x*256 + threadIdx.x)*4;
    if (v >= VP) return;
    float pg = g_pgen[b];
    if (v < V) {
        float4 e4 = *(const float4*)&g_logits[(size_t)b*V + v];
        float sc = g_scale[b*NBLK4 + (v >> 5)];
        float4 p;
        p.x = e4.x*sc; p.y = e4.y*sc; p.z = e4.z*sc; p.w = e4.w*sc;
        *(float4*)&out[OUT_PVOCAB + (size_t)b*V + v] = p;
        float2 f0 = make_float2(p.x*pg, p.y*pg);
        float2 f1 = make_float2(p.z*pg, p.w*pg);
        *(float2*)&out[OUT_PFINAL + (size_t)b*VP + v]     = f0;
        *(float2*)&out[OUT_PFINAL + (size_t)b*VP + v + 2] = f1;
    } else {
        #pragma unroll
        for (int i = 0; i < 4; i += 2)
            if (v + i < VP)
                *(float2*)&out[OUT_PFINAL + (size_t)b*VP + v + i] = make_float2(0.f, 0.f);
    }
}

// ---------------- F: pointer scatter ------------------------------------------
__global__ void k_scatter(const int* __restrict__ fiv, float* __restrict__ out) {
    int b = blockIdx.x;
    float w = 1.f - g_pgen[b];
    for (int s = threadIdx.x; s < S; s += blockDim.x) {
        int idx = fiv[b*S + s];
        atomicAdd(&out[OUT_PFINAL + (size_t)b*VP + idx], w*g_ad[b*S + s]);
    }
}

// ---------------- launcher ---------------------------------------------------
extern "C" void kernel_launch(void* const* d_in, const int* in_sizes, int n_in,
                              void* d_out, int out_size) {
    const int*   tok   = (const int*)  d_in[0];
    const float* hprev = (const float*)d_in[1];
    const float* enc   = (const float*)d_in[2];
    const int*   fiv   = (const int*)  d_in[3];
    const float* emb   = (const float*)d_in[4];
    const float* Wih   = (const float*)d_in[5];
    const float* Whh   = (const float*)d_in[6];
    const float* bih   = (const float*)d_in[7];
    const float* bhh   = (const float*)d_in[8];
    const float* wh    = (const float*)d_in[9];
    const float* ws    = (const float*)d_in[10];
    const float* ab    = (const float*)d_in[11];
    const float* av    = (const float*)d_in[12];
    const float* genw  = (const float*)d_in[13];
    const float* genb  = (const float*)d_in[14];
    const float* outhw = (const float*)d_in[15];
    const float* outhb = (const float*)d_in[16];
    const float* Wv    = (const float*)d_in[17];
    const float* bv    = (const float*)d_in[18];
    float* out = (float*)d_out;

    cudaFuncSetAttribute(k_logits, cudaFuncAttributeMaxDynamicSharedMemorySize, SMEM_D1);
    cudaFuncSetAttribute(k_part,   cudaFuncAttributeMaxDynamicSharedMemorySize, SMEM_P);

    k_gates   <<<dim3(12, 8), 256>>>(tok, emb, hprev, Wih, Whh, bih, bhh);
    k_part    <<<dim3(NCH, B), 256, SMEM_P>>>(enc, wh, ws, ab, av, hprev, out);
    k_comb_att<<<dim3(8, B), 256>>>(outhw, outhb, genw, genb, out);
    k_logits  <<<NBLK, 256, SMEM_D1>>>(Wv, bv);
    k_comb    <<<B, 256>>>();
    k_final   <<<dim3((VP + 1023)/1024, B), 256>>>(out);
    k_scatter <<<B, 256>>>(fiv, out);
}